// round 14
// baseline (speedup 1.0000x reference)
#include <cuda_runtime.h>

// Rotated-BEV IoU loss — ONE kernel, one block per SM (single wave),
// 16 rows/block, 512 threads, direct in-place clip (no compaction).

#define EPSF 1e-8f
#define MAXN 8192
#define ROWS_PB 16
#define GTILE 512
#define BLOCK 512

__device__ float g_row[MAXN];   // per-row |iou_pred - target|
__device__ int   g_done = 0;    // last-block counter (reset by reducer)

// ---------------------------------------------------------------------------
// Sum of cross(P,Q) over edges of polygon P (4 verts, CCW) clipped to the
// inside of polygon Q (4 verts, CCW). Register-resident, branch-free.
// STRICT=true uses half-open boundary for exactly-collinear edges (B pass).
template <bool STRICT>
__device__ __forceinline__ float clip_edges_sum(
    const float* __restrict__ Px, const float* __restrict__ Py,
    const float* __restrict__ Qx, const float* __restrict__ Qy)
{
    float tot = 0.0f;
#pragma unroll
    for (int i = 0; i < 4; ++i) {
        const float p1x = Px[i], p1y = Py[i];
        const float dax = Px[(i + 1) & 3] - p1x;
        const float day = Py[(i + 1) & 3] - p1y;
        float t0 = 0.0f, t1 = 1.0f;
#pragma unroll
        for (int j = 0; j < 4; ++j) {
            const float qx = Qx[j], qy = Qy[j];
            const float dbx = Qx[(j + 1) & 3] - qx;
            const float dby = Qy[(j + 1) & 3] - qy;
            // constraint: c0 + t*c1 >= 0  (inside = left of Q edge)
            const float c1 = dbx * day - dby * dax;
            const float c0 = dbx * (p1y - qy) - dby * (p1x - qx);
            const float tc = __fdividef(-c0, c1);
            if (c1 > 0.0f)      t0 = fmaxf(t0, tc);
            else if (c1 < 0.0f) t1 = fminf(t1, tc);
            else if (STRICT ? (c0 <= 0.0f) : (c0 < 0.0f)) t1 = -1.0f;
        }
        if (t1 > t0) {
            const float sx = fmaf(t0, dax, p1x), sy = fmaf(t0, day, p1y);
            const float ex = fmaf(t1, dax, p1x), ey = fmaf(t1, day, p1y);
            tot += sx * ey - sy * ex;
        }
    }
    return tot;
}

// ---------------------------------------------------------------------------
__global__ void __launch_bounds__(BLOCK)
fused_kernel(const float* __restrict__ iou_pred,
             const float* __restrict__ box_pred,
             const float* __restrict__ box_gt,
             float* __restrict__ out,
             const int* __restrict__ ntp_ptr, int has_ntp,
             int N, int M)
{
    // pred rows (block-exclusive)
    __shared__ float prx[ROWS_PB], pry[ROWS_PB], prex[ROWS_PB], prey[ROWS_PB];
    __shared__ float parea[ROWS_PB];
    __shared__ float pcx[ROWS_PB][4], pcy[ROWS_PB][4];
    __shared__ int   rowmaxbits[ROWS_PB];

    const int tid = threadIdx.x;
    const int lane = tid & 31;
    const int row0 = blockIdx.x * ROWS_PB;
    const int nrows = min(ROWS_PB, N - row0);

    // ---- pred-row prep ----
    if (tid < ROWS_PB) {
        rowmaxbits[tid] = 0;
        const int row = row0 + tid;
        if (row < N) {
            const float* b = box_pred + (size_t)row * 7;
            const float x = b[0], y = b[1];
            const float hx = 0.5f * b[3], hy = 0.5f * b[4];
            float s, c;
            __sincosf(b[6], &s, &c);
            prx[tid] = x; pry[tid] = y;
            prex[tid] = hx * fabsf(c) + hy * fabsf(s) + 1e-4f;
            prey[tid] = hx * fabsf(s) + hy * fabsf(c) + 1e-4f;
            parea[tid] = b[3] * b[4];
            pcx[tid][0] = x + c * hx - s * hy;  pcy[tid][0] = y + s * hx + c * hy;
            pcx[tid][1] = x - c * hx - s * hy;  pcy[tid][1] = y - s * hx + c * hy;
            pcx[tid][2] = x - c * hx + s * hy;  pcy[tid][2] = y - s * hx - c * hy;
            pcx[tid][3] = x + c * hx + s * hy;  pcy[tid][3] = y + s * hx - c * hy;
        }
    }
    __syncthreads();

    // ---- each thread owns gt boxes j = tid, tid+BLOCK, ... ----
    for (int j = tid; j < M; j += BLOCK) {
        const float* b = box_gt + (size_t)j * 7;
        const float gx = b[0], gy = b[1];
        const float hx = 0.5f * b[3], hy = 0.5f * b[4];
        float s, c;
        __sincosf(b[6], &s, &c);
        const float gex = hx * fabsf(c) + hy * fabsf(s) + 1e-4f;
        const float gey = hx * fabsf(s) + hy * fabsf(c) + 1e-4f;
        const float areaB = 4.0f * hx * hy;

        // B corners in registers (once per gt box)
        float Bx[4], By[4];
        Bx[0] = gx + c * hx - s * hy;  By[0] = gy + s * hx + c * hy;
        Bx[1] = gx - c * hx - s * hy;  By[1] = gy - s * hx + c * hy;
        Bx[2] = gx - c * hx + s * hy;  By[2] = gy - s * hx - c * hy;
        Bx[3] = gx + c * hx + s * hy;  By[3] = gy + s * hx - c * hy;

        for (int r = 0; r < nrows; ++r) {
            const bool pass = (fabsf(prx[r] - gx) <= prex[r] + gex) &
                              (fabsf(pry[r] - gy) <= prey[r] + gey);
            if (pass) {
                float Ax[4], Ay[4];
#pragma unroll
                for (int k = 0; k < 4; ++k) { Ax[k] = pcx[r][k]; Ay[k] = pcy[r][k]; }
                const float twoA = clip_edges_sum<false>(Ax, Ay, Bx, By)
                                 + clip_edges_sum<true >(Bx, By, Ax, Ay);
                const float inter = 0.5f * fmaxf(twoA, 0.0f);
                if (inter > 0.0f) {
                    const float uni = fmaxf(parea[r] + areaB - inter, EPSF);
                    atomicMax(&rowmaxbits[r], __float_as_int(inter / uni));
                }
            }
        }
    }
    __syncthreads();

    if (tid < nrows) {
        const int row = row0 + tid;
        const float mx = __int_as_float(rowmaxbits[tid]);
        g_row[row] = fabsf(iou_pred[row] - (2.0f * mx - 1.0f));
    }

    // ---- last finished block does the deterministic final reduction ----
    __shared__ int isLast;
    if (tid == 0) {
        __threadfence();
        isLast = (atomicAdd(&g_done, 1) == (int)gridDim.x - 1);
    }
    __syncthreads();
    if (!isLast) return;
    __threadfence();

    float sum = 0.0f;
    for (int i = tid; i < N; i += BLOCK) sum += g_row[i];
#pragma unroll
    for (int o = 16; o > 0; o >>= 1)
        sum += __shfl_down_sync(0xFFFFFFFFu, sum, o);

    __shared__ float wsum[BLOCK / 32];
    if (lane == 0) wsum[tid >> 5] = sum;
    __syncthreads();
    if (tid == 0) {
        float tot = 0.0f;
#pragma unroll
        for (int w = 0; w < BLOCK / 32; ++w) tot += wsum[w];
        float ntp = 2048.0f;
        if (has_ntp) {
            const int iv = *ntp_ptr;
            if (iv > 0 && iv < 100000000) ntp = (float)iv;
            else ntp = __int_as_float(iv);
        }
        out[0] = tot / (ntp + 1e-4f);
        g_done = 0;   // reset for next graph replay
    }
}

// ---------------------------------------------------------------------------
extern "C" void kernel_launch(void* const* d_in, const int* in_sizes, int n_in,
                              void* d_out, int out_size)
{
    const float* iou_pred = (const float*)d_in[0];
    const float* box_pred = (const float*)d_in[1];
    const float* box_gt   = (const float*)d_in[2];
    const int N = in_sizes[1] / 7;
    const int M = in_sizes[2] / 7;
    const int* ntp_ptr = (n_in >= 4) ? (const int*)d_in[3] : nullptr;
    const int has_ntp = (n_in >= 4) ? 1 : 0;

    const int grid = (N + ROWS_PB - 1) / ROWS_PB;   // 128 blocks for N=2048
    fused_kernel<<<grid, BLOCK>>>(iou_pred, box_pred, box_gt, (float*)d_out,
                                  ntp_ptr, has_ntp, N, M);
}

// round 15
// speedup vs baseline: 1.8534x; 1.8534x over previous
#include <cuda_runtime.h>

// Rotated-BEV IoU loss — ONE kernel, one block per SM, 16 rows/block,
// warp-private compaction (no atomics), register-only clip.

#define EPSF 1e-8f
#define MAXN 8192
#define ROWS_PB 16
#define BLOCK 512
#define NWARP (BLOCK / 32)
#define WCAP  (ROWS_PB * 32)   // worst-case survivors per warp per trip

__device__ float g_row[MAXN];   // per-row |iou_pred - target|
__device__ int   g_done = 0;    // last-block counter (reset by reducer)

// ---------------------------------------------------------------------------
// Sum of cross(P,Q) over edges of polygon P (4 verts, CCW) clipped to the
// inside of polygon Q (4 verts, CCW). Register-resident, branch-free.
// STRICT=true uses half-open boundary for exactly-collinear edges (B pass).
template <bool STRICT>
__device__ __forceinline__ float clip_edges_sum(
    const float* __restrict__ Px, const float* __restrict__ Py,
    const float* __restrict__ Qx, const float* __restrict__ Qy)
{
    float tot = 0.0f;
#pragma unroll
    for (int i = 0; i < 4; ++i) {
        const float p1x = Px[i], p1y = Py[i];
        const float dax = Px[(i + 1) & 3] - p1x;
        const float day = Py[(i + 1) & 3] - p1y;
        float t0 = 0.0f, t1 = 1.0f;
#pragma unroll
        for (int j = 0; j < 4; ++j) {
            const float qx = Qx[j], qy = Qy[j];
            const float dbx = Qx[(j + 1) & 3] - qx;
            const float dby = Qy[(j + 1) & 3] - qy;
            // constraint: c0 + t*c1 >= 0  (inside = left of Q edge)
            const float c1 = dbx * day - dby * dax;
            const float c0 = dbx * (p1y - qy) - dby * (p1x - qx);
            const float tc = __fdividef(-c0, c1);
            if (c1 > 0.0f)      t0 = fmaxf(t0, tc);
            else if (c1 < 0.0f) t1 = fminf(t1, tc);
            else if (STRICT ? (c0 <= 0.0f) : (c0 < 0.0f)) t1 = -1.0f;
        }
        if (t1 > t0) {
            const float sx = fmaf(t0, dax, p1x), sy = fmaf(t0, day, p1y);
            const float ex = fmaf(t1, dax, p1x), ey = fmaf(t1, day, p1y);
            tot += sx * ey - sy * ex;
        }
    }
    return tot;
}

// ---------------------------------------------------------------------------
__global__ void __launch_bounds__(BLOCK)
fused_kernel(const float* __restrict__ iou_pred,
             const float* __restrict__ box_pred,
             const float* __restrict__ box_gt,
             float* __restrict__ out,
             const int* __restrict__ ntp_ptr, int has_ntp,
             int N, int M)
{
    // gt tile params (per trip): 6 * 512 * 4 = 12 KB
    __shared__ float sgx[BLOCK], sgy[BLOCK], sghx[BLOCK], sghy[BLOCK];
    __shared__ float sgc[BLOCK], sgs[BLOCK];
    // pred rows (block-exclusive)
    __shared__ float prx[ROWS_PB], pry[ROWS_PB], prex[ROWS_PB], prey[ROWS_PB];
    __shared__ float parea[ROWS_PB];
    __shared__ float pcx[ROWS_PB][4], pcy[ROWS_PB][4];
    __shared__ int   rowmaxbits[ROWS_PB];
    // per-warp survivor lists (16 warps * 512 * 2B = 16 KB)
    __shared__ unsigned short slist[NWARP * WCAP];

    const int tid = threadIdx.x;
    const int lane = tid & 31;
    const int wid = tid >> 5;
    const int row0 = blockIdx.x * ROWS_PB;
    const int nrows = min(ROWS_PB, N - row0);
    unsigned short* wlist = slist + wid * WCAP;

    // ---- pred-row prep ----
    if (tid < ROWS_PB) {
        rowmaxbits[tid] = 0;
        const int row = row0 + tid;
        if (row < N) {
            const float* b = box_pred + (size_t)row * 7;
            const float x = b[0], y = b[1];
            const float hx = 0.5f * b[3], hy = 0.5f * b[4];
            float s, c;
            __sincosf(b[6], &s, &c);
            prx[tid] = x; pry[tid] = y;
            prex[tid] = hx * fabsf(c) + hy * fabsf(s) + 1e-4f;
            prey[tid] = hx * fabsf(s) + hy * fabsf(c) + 1e-4f;
            parea[tid] = b[3] * b[4];
            pcx[tid][0] = x + c * hx - s * hy;  pcy[tid][0] = y + s * hx + c * hy;
            pcx[tid][1] = x - c * hx - s * hy;  pcy[tid][1] = y - s * hx + c * hy;
            pcx[tid][2] = x - c * hx + s * hy;  pcy[tid][2] = y - s * hx - c * hy;
            pcx[tid][3] = x + c * hx + s * hy;  pcy[tid][3] = y + s * hx - c * hy;
        }
    }

    // ---- trips over gt boxes (single trip for M <= 512) ----
    for (int jt = 0; jt < M; jt += BLOCK) {
        const int j = jt + tid;
        const bool jv = (j < M);

        // stage this thread's gt box (regs + smem)
        float gx = 0.f, gy = 0.f, hx = 0.f, hy = 0.f, c = 1.f, s = 0.f;
        float gex = -1e30f, gey = -1e30f;
        __syncthreads();
        if (jv) {
            const float* b = box_gt + (size_t)j * 7;
            gx = b[0]; gy = b[1];
            hx = 0.5f * b[3]; hy = 0.5f * b[4];
            __sincosf(b[6], &s, &c);
            gex = hx * fabsf(c) + hy * fabsf(s) + 1e-4f;
            gey = hx * fabsf(s) + hy * fabsf(c) + 1e-4f;
            sgx[tid] = gx; sgy[tid] = gy;
            sghx[tid] = hx; sghy[tid] = hy;
            sgc[tid] = c; sgs[tid] = s;
        }
        __syncthreads();

        // ---- warp-private compaction: no atomics ----
        int wcnt = 0;
        for (int r = 0; r < nrows; ++r) {
            const bool pass = jv &
                (fabsf(prx[r] - gx) <= prex[r] + gex) &
                (fabsf(pry[r] - gy) <= prey[r] + gey);
            const unsigned msk = __ballot_sync(0xFFFFFFFFu, pass);
            if (pass)
                wlist[wcnt + __popc(msk & ((1u << lane) - 1u))] =
                    (unsigned short)((r << 9) | tid);   // tile-local j == tid
            wcnt += __popc(msk);
        }
        __syncwarp();

        // ---- warp clips its own list ----
        for (int i = lane; i < wcnt; i += 32) {
            const int pk = wlist[i];
            const int r = pk >> 9;
            const int jl = pk & 0x1FF;
            float Ax[4], Ay[4], Bx[4], By[4];
#pragma unroll
            for (int k = 0; k < 4; ++k) { Ax[k] = pcx[r][k]; Ay[k] = pcy[r][k]; }
            const float x2 = sgx[jl], y2 = sgy[jl];
            const float h2 = sghx[jl], v2 = sghy[jl];
            const float c2 = sgc[jl], s2 = sgs[jl];
            Bx[0] = x2 + c2 * h2 - s2 * v2;  By[0] = y2 + s2 * h2 + c2 * v2;
            Bx[1] = x2 - c2 * h2 - s2 * v2;  By[1] = y2 - s2 * h2 + c2 * v2;
            Bx[2] = x2 - c2 * h2 + s2 * v2;  By[2] = y2 - s2 * h2 - c2 * v2;
            Bx[3] = x2 + c2 * h2 + s2 * v2;  By[3] = y2 + s2 * h2 - c2 * v2;

            const float twoA = clip_edges_sum<false>(Ax, Ay, Bx, By)
                             + clip_edges_sum<true >(Bx, By, Ax, Ay);
            const float inter = 0.5f * fmaxf(twoA, 0.0f);
            if (inter > 0.0f) {
                const float uni = fmaxf(parea[r] + 4.0f * h2 * v2 - inter, EPSF);
                atomicMax(&rowmaxbits[r], __float_as_int(inter / uni));
            }
        }
    }
    __syncthreads();

    if (tid < nrows) {
        const int row = row0 + tid;
        const float mx = __int_as_float(rowmaxbits[tid]);
        g_row[row] = fabsf(iou_pred[row] - (2.0f * mx - 1.0f));
    }

    // ---- last finished block does the deterministic final reduction ----
    __shared__ int isLast;
    if (tid == 0) {
        __threadfence();
        isLast = (atomicAdd(&g_done, 1) == (int)gridDim.x - 1);
    }
    __syncthreads();
    if (!isLast) return;
    __threadfence();

    float sum = 0.0f;
    for (int i = tid; i < N; i += BLOCK) sum += g_row[i];
#pragma unroll
    for (int o = 16; o > 0; o >>= 1)
        sum += __shfl_down_sync(0xFFFFFFFFu, sum, o);

    __shared__ float wsum[NWARP];
    if (lane == 0) wsum[wid] = sum;
    __syncthreads();
    if (tid == 0) {
        float tot = 0.0f;
#pragma unroll
        for (int w = 0; w < NWARP; ++w) tot += wsum[w];
        float ntp = 2048.0f;
        if (has_ntp) {
            const int iv = *ntp_ptr;
            if (iv > 0 && iv < 100000000) ntp = (float)iv;
            else ntp = __int_as_float(iv);
        }
        out[0] = tot / (ntp + 1e-4f);
        g_done = 0;   // reset for next graph replay
    }
}

// ---------------------------------------------------------------------------
extern "C" void kernel_launch(void* const* d_in, const int* in_sizes, int n_in,
                              void* d_out, int out_size)
{
    const float* iou_pred = (const float*)d_in[0];
    const float* box_pred = (const float*)d_in[1];
    const float* box_gt   = (const float*)d_in[2];
    const int N = in_sizes[1] / 7;
    const int M = in_sizes[2] / 7;
    const int* ntp_ptr = (n_in >= 4) ? (const int*)d_in[3] : nullptr;
    const int has_ntp = (n_in >= 4) ? 1 : 0;

    const int grid = (N + ROWS_PB - 1) / ROWS_PB;   // 128 blocks for N=2048
    fused_kernel<<<grid, BLOCK>>>(iou_pred, box_pred, box_gt, (float*)d_out,
                                  ntp_ptr, has_ntp, N, M);
}